// round 1
// baseline (speedup 1.0000x reference)
#include <cuda_runtime.h>

#define B 256
#define S 512
#define IN_F 32
#define H 256
#define G3 768
#define D_OUT 32
#define NSTATE 4
#define PRED 96

#define GRU_CTAS 128
#define ROWTILES 16
#define STRIPS 8
#define ROWS_PER_CTA 16
#define SW_STRIDE 260  // 260 % 32 == 4 -> conflict-free LDS.128 across 32 strip lanes
#define SMEM_BYTES ((96 * SW_STRIDE + ROWS_PER_CTA * H) * 4)

// -------- scratch (device globals; no runtime allocation allowed) --------
__device__ float g_xp[(size_t)B * S * G3];    // 402 MB, reused for xp0 then xp1
__device__ float g_h1s[(size_t)B * S * H];    // 134 MB, layer-0 hidden sequence
__device__ float g_hbuf[2 * B * H];           // double-buffered recurrent h
__device__ float g_h2[B * H];                 // final layer-1 h
__device__ unsigned g_bar_count[ROWTILES];
__device__ unsigned g_bar_gen[ROWTILES];

// -------- generic tiled SGEMM: out[M,N] = A[M,K] @ W[N,K]^T + bias[N] --------
// Requires M%64==0, N%64==0, K%16==0 (all shapes here satisfy this).
__global__ __launch_bounds__(256) void gemm_nt_bias(
    const float* __restrict__ A, const float* __restrict__ W,
    const float* __restrict__ bias, float* __restrict__ out,
    int M, int N, int K)
{
    __shared__ float As[16][64];
    __shared__ float Ws[16][64];
    const int n0 = blockIdx.x * 64;
    const int m0 = blockIdx.y * 64;
    const int tid = threadIdx.x;
    const int lr = tid >> 2;
    const int lk = (tid & 3) << 2;
    const int tx = tid & 15;
    const int ty = tid >> 4;

    float acc[4][4];
#pragma unroll
    for (int i = 0; i < 4; i++)
#pragma unroll
        for (int j = 0; j < 4; j++) acc[i][j] = 0.f;

    for (int k0 = 0; k0 < K; k0 += 16) {
        float4 a = *(const float4*)&A[(size_t)(m0 + lr) * K + k0 + lk];
        float4 w = *(const float4*)&W[(size_t)(n0 + lr) * K + k0 + lk];
        As[lk + 0][lr] = a.x; As[lk + 1][lr] = a.y; As[lk + 2][lr] = a.z; As[lk + 3][lr] = a.w;
        Ws[lk + 0][lr] = w.x; Ws[lk + 1][lr] = w.y; Ws[lk + 2][lr] = w.z; Ws[lk + 3][lr] = w.w;
        __syncthreads();
#pragma unroll
        for (int k = 0; k < 16; k++) {
            float4 av = *(const float4*)&As[k][ty * 4];
            float4 wv = *(const float4*)&Ws[k][tx * 4];
            float am[4] = {av.x, av.y, av.z, av.w};
            float wm[4] = {wv.x, wv.y, wv.z, wv.w};
#pragma unroll
            for (int i = 0; i < 4; i++)
#pragma unroll
                for (int j = 0; j < 4; j++) acc[i][j] += am[i] * wm[j];
        }
        __syncthreads();
    }
#pragma unroll
    for (int i = 0; i < 4; i++) {
        int m = m0 + ty * 4 + i;
#pragma unroll
        for (int j = 0; j < 4; j++) {
            int n = n0 + tx * 4 + j;
            out[(size_t)m * N + n] = acc[i][j] + bias[n];
        }
    }
}

// -------- 8-CTA row-group sense barrier --------
__device__ __forceinline__ void group_barrier(int g, unsigned target)
{
    __syncthreads();
    if (threadIdx.x == 0) {
        __threadfence();
        unsigned prev = atomicAdd(&g_bar_count[g], 1u);
        if (prev == STRIPS - 1) {
            atomicExch(&g_bar_count[g], 0u);
            __threadfence();
            atomicAdd(&g_bar_gen[g], 1u);
        } else {
            while (*((volatile unsigned*)&g_bar_gen[g]) < target) { }
            __threadfence();
        }
    }
    __syncthreads();
}

// -------- persistent GRU layer --------
// Grid: 128 CTAs = 16 row-tiles (16 batch rows each) x 8 col-strips (32 cols of each gate).
// Each CTA caches its W_hh slice (r/z/n strips) in smem for all 512 steps.
// Gating is CTA-local; one 8-CTA barrier per step.
__global__ __launch_bounds__(128, 1) void gru_layer(
    const float* __restrict__ xp,   // [B*S, 768] = x-projection incl. b_ih
    const float* __restrict__ Whh,  // [768, 256]
    const float* __restrict__ bhh,  // [768]
    float* __restrict__ h_seq,      // [B*S, 256] or null
    float* __restrict__ h_final)    // [B, 256] or null
{
    extern __shared__ float sm[];
    float* sW = sm;                       // [96][SW_STRIDE]
    float* sH = sm + 96 * SW_STRIDE;      // [16][256]

    const int cta = blockIdx.x;
    const int rowtile = cta >> 3;
    const int strip = cta & 7;
    const int j0 = strip * 32;
    const int r0 = rowtile * ROWS_PER_CTA;
    const int tid = threadIdx.x;
    const int j = tid & 31;
    const int rq = tid >> 5;   // warp id: owns rows r0+rq*4 .. +3
    const int jj = j0 + j;

    // Preload W_hh strips (gate g, cols j0..j0+31) once.
    for (int i = tid; i < 96 * 64; i += 128) {
        int wrow = i >> 6;            // g*32 + jc
        int k4 = (i & 63) << 2;
        int g = wrow >> 5, jc = wrow & 31;
        float4 v = *(const float4*)&Whh[(size_t)(g * H + j0 + jc) * H + k4];
        *(float4*)&sW[wrow * SW_STRIDE + k4] = v;
    }
    const float bhr = bhh[jj];
    const float bhz = bhh[H + jj];
    const float bhn = bhh[2 * H + jj];

    // h0 = 0 for this CTA's (rows x cols) slice of buffer 0.
#pragma unroll
    for (int i = 0; i < 4; i++) {
        int row = r0 + rq * 4 + i;
        g_hbuf[(size_t)row * H + jj] = 0.f;
    }

    unsigned target = *((volatile unsigned*)&g_bar_gen[rowtile]);
    target++;
    group_barrier(rowtile, target);   // zeros + smem W visible

    for (int t = 0; t < S; t++) {
        const float* hcur = g_hbuf + (size_t)(t & 1) * (B * H);
        float* hnext = g_hbuf + (size_t)((t + 1) & 1) * (B * H);

        // Stage this tile's 16 h rows (L2-coherent: peers wrote them).
        for (int i = tid; i < ROWS_PER_CTA * 64; i += 128) {
            int rr = i >> 6, k4 = (i & 63) << 2;
            float4 v = __ldcg((const float4*)&hcur[(size_t)(r0 + rr) * H + k4]);
            *(float4*)&sH[rr * H + k4] = v;
        }
        __syncthreads();

        float ar[4] = {0, 0, 0, 0}, az[4] = {0, 0, 0, 0}, an[4] = {0, 0, 0, 0};
        const float* wr = sW + j * SW_STRIDE;
        const float* wz = sW + (32 + j) * SW_STRIDE;
        const float* wn = sW + (64 + j) * SW_STRIDE;
        const float* hb = sH + rq * 4 * H;

#pragma unroll 8
        for (int k = 0; k < H; k += 4) {
            float4 wrv = *(const float4*)(wr + k);
            float4 wzv = *(const float4*)(wz + k);
            float4 wnv = *(const float4*)(wn + k);
#pragma unroll
            for (int i = 0; i < 4; i++) {
                float4 hv = *(const float4*)(hb + i * H + k);   // warp-broadcast
                ar[i] += hv.x * wrv.x + hv.y * wrv.y + hv.z * wrv.z + hv.w * wrv.w;
                az[i] += hv.x * wzv.x + hv.y * wzv.y + hv.z * wzv.z + hv.w * wzv.w;
                an[i] += hv.x * wnv.x + hv.y * wnv.y + hv.z * wnv.z + hv.w * wnv.w;
            }
        }

#pragma unroll
        for (int i = 0; i < 4; i++) {
            int row = r0 + rq * 4 + i;
            size_t xb = ((size_t)row * S + t) * G3 + jj;
            float xr = __ldg(&xp[xb]);
            float xz = __ldg(&xp[xb + H]);
            float xn = __ldg(&xp[xb + 2 * H]);
            float rg = 1.f / (1.f + __expf(-(xr + ar[i] + bhr)));
            float zg = 1.f / (1.f + __expf(-(xz + az[i] + bhz)));
            float ng = tanhf(xn + rg * (an[i] + bhn));
            float hold = sH[(rq * 4 + i) * H + jj];
            float hnew = (1.f - zg) * ng + zg * hold;
            hnext[(size_t)row * H + jj] = hnew;
            if (h_seq) h_seq[((size_t)row * S + t) * H + jj] = hnew;
            if (h_final && t == S - 1) h_final[(size_t)row * H + jj] = hnew;
        }

        target++;
        group_barrier(rowtile, target);
    }
}

// -------- projection + 96-step diagonal forecast, fused --------
__global__ void forecast_kernel(
    const float* __restrict__ h2, const float* __restrict__ Wp,
    const float* __restrict__ bp, const float* __restrict__ C,
    const float* __restrict__ rld, const float* __restrict__ rtd,
    const float* __restrict__ rg_, const float* __restrict__ om,
    float* __restrict__ out)
{
    const int b = blockIdx.x;   // 256
    const int d = threadIdx.x;  // 32
    __shared__ float sh[H];
    for (int i = d; i < H; i += 32) sh[i] = h2[(size_t)b * H + i];
    __syncthreads();

    float s[NSTATE];
#pragma unroll
    for (int st = 0; st < NSTATE; st++) {
        const float* w = Wp + (size_t)(d * NSTATE + st) * H;
        float acc = bp[d * NSTATE + st];
        for (int k = 0; k < H; k += 4) {
            float4 wv = *(const float4*)(w + k);
            acc += sh[k] * wv.x + sh[k + 1] * wv.y + sh[k + 2] * wv.z + sh[k + 3] * wv.w;
        }
        s[st] = acc;
    }

    float al = 1.f / (1.f + expf(-rld[d])) * 0.15f + 0.85f;
    float at = 1.f / (1.f + expf(-rtd[d])) * 0.25f + 0.70f;
    float gg = 1.f / (1.f + expf(-rg_[d])) * 0.20f + 0.80f;
    float c = cosf(om[d]), sn = sinf(om[d]);
    float r00 = gg * c, r01 = -gg * sn, r10 = gg * sn, r11 = gg * c;
    float C0 = C[d * 4 + 0], C1 = C[d * 4 + 1], C2 = C[d * 4 + 2], C3 = C[d * 4 + 3];

    for (int p = 0; p < PRED; p++) {
        float n0 = s[0] * al;
        float n1 = s[1] * at;
        float n2 = s[2] * r00 + s[3] * r10;
        float n3 = s[2] * r01 + s[3] * r11;
        s[0] = n0; s[1] = n1; s[2] = n2; s[3] = n3;
        out[((size_t)b * PRED + p) * D_OUT + d] = C0 * n0 + C1 * n1 + C2 * n2 + C3 * n3;
    }
}

extern "C" void kernel_launch(void* const* d_in, const int* in_sizes, int n_in,
                              void* d_out, int out_size)
{
    const float* x    = (const float*)d_in[0];
    const float* Wih0 = (const float*)d_in[1];
    const float* Whh0 = (const float*)d_in[2];
    const float* bih0 = (const float*)d_in[3];
    const float* bhh0 = (const float*)d_in[4];
    const float* Wih1 = (const float*)d_in[5];
    const float* Whh1 = (const float*)d_in[6];
    const float* bih1 = (const float*)d_in[7];
    const float* bhh1 = (const float*)d_in[8];
    const float* Wp   = (const float*)d_in[9];
    const float* bp   = (const float*)d_in[10];
    const float* C    = (const float*)d_in[11];
    const float* rld  = (const float*)d_in[12];
    const float* rtd  = (const float*)d_in[13];
    const float* rg   = (const float*)d_in[14];
    const float* om   = (const float*)d_in[15];
    float* out = (float*)d_out;

    float *xp, *h1s, *h2;
    cudaGetSymbolAddress((void**)&xp, g_xp);
    cudaGetSymbolAddress((void**)&h1s, g_h1s);
    cudaGetSymbolAddress((void**)&h2, g_h2);

    cudaFuncSetAttribute(gru_layer, cudaFuncAttributeMaxDynamicSharedMemorySize, SMEM_BYTES);

    dim3 gg(G3 / 64, (B * S) / 64);

    // xp0 = x @ W_ih0^T + b_ih0
    gemm_nt_bias<<<gg, 256>>>(x, Wih0, bih0, xp, B * S, G3, IN_F);
    // layer 0 recurrence -> h1s
    gru_layer<<<GRU_CTAS, 128, SMEM_BYTES>>>(xp, Whh0, bhh0, h1s, nullptr);
    // xp1 = h1s @ W_ih1^T + b_ih1 (reuse xp buffer)
    gemm_nt_bias<<<gg, 256>>>(h1s, Wih1, bih1, xp, B * S, G3, H);
    // layer 1 recurrence -> h2 (final step only)
    gru_layer<<<GRU_CTAS, 128, SMEM_BYTES>>>(xp, Whh1, bhh1, nullptr, h2);
    // projection + forecast
    forecast_kernel<<<B, 32>>>(h2, Wp, bp, C, rld, rtd, rg, om, out);
}

// round 2
// speedup vs baseline: 1.3307x; 1.3307x over previous
#include <cuda_runtime.h>

#define B 256
#define S 512
#define IN_F 32
#define H 256
#define G3 768
#define D_OUT 32
#define NSTATE 4
#define PRED 96

#define GRU_CTAS 128
#define ROWTILES 16
#define STRIPS 8
#define ROWS_PER_CTA 16
#define SW_STRIDE 260  // 260 % 32 == 4 -> conflict-free LDS.128 across 32 strip lanes
#define SMEM_BYTES ((96 * SW_STRIDE + ROWS_PER_CTA * H) * 4)

// -------- packed f32x2 helpers (sm_103a FFMA2 path) --------
__device__ __forceinline__ unsigned long long fma2(unsigned long long a,
                                                   unsigned long long b,
                                                   unsigned long long c)
{
    unsigned long long d;
    asm("fma.rn.f32x2 %0, %1, %2, %3;" : "=l"(d) : "l"(a), "l"(b), "l"(c));
    return d;
}
__device__ __forceinline__ unsigned long long dup2(float x)
{
    unsigned long long d;
    unsigned r = __float_as_uint(x);
    asm("mov.b64 %0, {%1, %1};" : "=l"(d) : "r"(r));
    return d;
}
__device__ __forceinline__ float hsum2(unsigned long long a)
{
    unsigned lo, hi;
    asm("mov.b64 {%0, %1}, %2;" : "=r"(lo), "=r"(hi) : "l"(a));
    return __uint_as_float(lo) + __uint_as_float(hi);
}
__device__ __forceinline__ void unpack2(unsigned long long a, float& lo, float& hi)
{
    unsigned l, h;
    asm("mov.b64 {%0, %1}, %2;" : "=r"(l), "=r"(h) : "l"(a));
    lo = __uint_as_float(l); hi = __uint_as_float(h);
}
__device__ __forceinline__ float tanh_ap(float x)
{
    float y;
    asm("tanh.approx.f32 %0, %1;" : "=f"(y) : "f"(x));
    return y;
}
__device__ __forceinline__ float sigmoid_ap(float x)
{
    return 0.5f * tanh_ap(0.5f * x) + 0.5f;
}

// -------- scratch (device globals; no runtime allocation allowed) --------
__device__ float g_xp[(size_t)B * S * G3];    // reused for xp0 then xp1
__device__ float g_h1s[(size_t)B * S * H];    // layer-0 hidden sequence
__device__ float g_hbuf[2 * B * H];           // double-buffered recurrent h
__device__ float g_h2[B * H];                 // final layer-1 h
__device__ unsigned g_bar_count[ROWTILES];
__device__ unsigned g_bar_gen[ROWTILES];

// -------- tiled SGEMM (packed-N f32x2): out[M,N] = A[M,K] @ W[N,K]^T + bias --------
__global__ __launch_bounds__(256) void gemm_nt_bias(
    const float* __restrict__ A, const float* __restrict__ W,
    const float* __restrict__ bias, float* __restrict__ out,
    int M, int N, int K)
{
    __shared__ float As[16][64];
    __shared__ float Ws[16][64];
    const int n0 = blockIdx.x * 64;
    const int m0 = blockIdx.y * 64;
    const int tid = threadIdx.x;
    const int lr = tid >> 2;
    const int lk = (tid & 3) << 2;
    const int tx = tid & 15;
    const int ty = tid >> 4;

    unsigned long long acc[4][2];   // 4 rows x 2 packed col-pairs (4 cols)
#pragma unroll
    for (int i = 0; i < 4; i++) { acc[i][0] = 0ull; acc[i][1] = 0ull; }

    for (int k0 = 0; k0 < K; k0 += 16) {
        float4 a = *(const float4*)&A[(size_t)(m0 + lr) * K + k0 + lk];
        float4 w = *(const float4*)&W[(size_t)(n0 + lr) * K + k0 + lk];
        As[lk + 0][lr] = a.x; As[lk + 1][lr] = a.y; As[lk + 2][lr] = a.z; As[lk + 3][lr] = a.w;
        Ws[lk + 0][lr] = w.x; Ws[lk + 1][lr] = w.y; Ws[lk + 2][lr] = w.z; Ws[lk + 3][lr] = w.w;
        __syncthreads();
#pragma unroll
        for (int k = 0; k < 16; k++) {
            float4 av = *(const float4*)&As[k][ty * 4];
            ulonglong2 wv = *(const ulonglong2*)&Ws[k][tx * 4];
            unsigned long long a0 = dup2(av.x), a1 = dup2(av.y),
                               a2 = dup2(av.z), a3 = dup2(av.w);
            acc[0][0] = fma2(a0, wv.x, acc[0][0]); acc[0][1] = fma2(a0, wv.y, acc[0][1]);
            acc[1][0] = fma2(a1, wv.x, acc[1][0]); acc[1][1] = fma2(a1, wv.y, acc[1][1]);
            acc[2][0] = fma2(a2, wv.x, acc[2][0]); acc[2][1] = fma2(a2, wv.y, acc[2][1]);
            acc[3][0] = fma2(a3, wv.x, acc[3][0]); acc[3][1] = fma2(a3, wv.y, acc[3][1]);
        }
        __syncthreads();
    }
#pragma unroll
    for (int i = 0; i < 4; i++) {
        int m = m0 + ty * 4 + i;
        float c0, c1, c2, c3;
        unpack2(acc[i][0], c0, c1);
        unpack2(acc[i][1], c2, c3);
        int n = n0 + tx * 4;
        float4 o;
        o.x = c0 + bias[n + 0];
        o.y = c1 + bias[n + 1];
        o.z = c2 + bias[n + 2];
        o.w = c3 + bias[n + 3];
        *(float4*)&out[(size_t)m * N + n] = o;
    }
}

// -------- 8-CTA row-group sense barrier --------
__device__ __forceinline__ void group_barrier(int g, unsigned target)
{
    __syncthreads();
    if (threadIdx.x == 0) {
        __threadfence();
        unsigned prev = atomicAdd(&g_bar_count[g], 1u);
        if (prev == STRIPS - 1) {
            atomicExch(&g_bar_count[g], 0u);
            __threadfence();
            atomicAdd(&g_bar_gen[g], 1u);
        } else {
            while (*((volatile unsigned*)&g_bar_gen[g]) < target) { }
            __threadfence();
        }
    }
    __syncthreads();
}

// -------- persistent GRU layer (packed-K f32x2 dot products) --------
__global__ __launch_bounds__(128, 1) void gru_layer(
    const float* __restrict__ xp,   // [B*S, 768] = x-projection incl. b_ih
    const float* __restrict__ Whh,  // [768, 256]
    const float* __restrict__ bhh,  // [768]
    float* __restrict__ h_seq,      // [B*S, 256] or null
    float* __restrict__ h_final)    // [B, 256] or null
{
    extern __shared__ float sm[];
    float* sW = sm;                       // [96][SW_STRIDE]
    float* sH = sm + 96 * SW_STRIDE;      // [16][256]

    const int cta = blockIdx.x;
    const int rowtile = cta >> 3;
    const int strip = cta & 7;
    const int j0 = strip * 32;
    const int r0 = rowtile * ROWS_PER_CTA;
    const int tid = threadIdx.x;
    const int j = tid & 31;
    const int rq = tid >> 5;   // warp id: owns rows r0+rq*4 .. +3
    const int jj = j0 + j;

    // Preload W_hh strips (gate g, cols j0..j0+31) once.
    for (int i = tid; i < 96 * 64; i += 128) {
        int wrow = i >> 6;            // g*32 + jc
        int k4 = (i & 63) << 2;
        int g = wrow >> 5, jc = wrow & 31;
        float4 v = *(const float4*)&Whh[(size_t)(g * H + j0 + jc) * H + k4];
        *(float4*)&sW[wrow * SW_STRIDE + k4] = v;
    }
    const float bhr = bhh[jj];
    const float bhz = bhh[H + jj];
    const float bhn = bhh[2 * H + jj];

#pragma unroll
    for (int i = 0; i < 4; i++) {
        int row = r0 + rq * 4 + i;
        g_hbuf[(size_t)row * H + jj] = 0.f;
    }

    unsigned target = *((volatile unsigned*)&g_bar_gen[rowtile]);
    target++;
    group_barrier(rowtile, target);   // zeros + smem W visible

    for (int t = 0; t < S; t++) {
        const float* hcur = g_hbuf + (size_t)(t & 1) * (B * H);
        float* hnext = g_hbuf + (size_t)((t + 1) & 1) * (B * H);

        // Prefetch this step's xp values FIRST (independent of h).
        float pxr[4], pxz[4], pxn[4];
#pragma unroll
        for (int i = 0; i < 4; i++) {
            size_t xb = ((size_t)(r0 + rq * 4 + i) * S + t) * G3 + jj;
            pxr[i] = __ldg(&xp[xb]);
            pxz[i] = __ldg(&xp[xb + H]);
            pxn[i] = __ldg(&xp[xb + 2 * H]);
        }

        // Stage this tile's 16 h rows (L2-coherent: peers wrote them).
        for (int i = tid; i < ROWS_PER_CTA * 64; i += 128) {
            int rr = i >> 6, k4 = (i & 63) << 2;
            float4 v = __ldcg((const float4*)&hcur[(size_t)(r0 + rr) * H + k4]);
            *(float4*)&sH[rr * H + k4] = v;
        }
        __syncthreads();

        unsigned long long ar2[4], az2[4], an2[4];
#pragma unroll
        for (int i = 0; i < 4; i++) { ar2[i] = 0ull; az2[i] = 0ull; an2[i] = 0ull; }

        const float* wr = sW + j * SW_STRIDE;
        const float* wz = sW + (32 + j) * SW_STRIDE;
        const float* wn = sW + (64 + j) * SW_STRIDE;
        const float* hb = sH + rq * 4 * H;

#pragma unroll 8
        for (int k = 0; k < H; k += 4) {
            ulonglong2 wrv = *(const ulonglong2*)(wr + k);
            ulonglong2 wzv = *(const ulonglong2*)(wz + k);
            ulonglong2 wnv = *(const ulonglong2*)(wn + k);
#pragma unroll
            for (int i = 0; i < 4; i++) {
                ulonglong2 hv = *(const ulonglong2*)(hb + i * H + k);  // warp-broadcast
                ar2[i] = fma2(hv.x, wrv.x, ar2[i]);
                az2[i] = fma2(hv.x, wzv.x, az2[i]);
                an2[i] = fma2(hv.x, wnv.x, an2[i]);
                ar2[i] = fma2(hv.y, wrv.y, ar2[i]);
                az2[i] = fma2(hv.y, wzv.y, az2[i]);
                an2[i] = fma2(hv.y, wnv.y, an2[i]);
            }
        }

#pragma unroll
        for (int i = 0; i < 4; i++) {
            int row = r0 + rq * 4 + i;
            float rg = sigmoid_ap(pxr[i] + hsum2(ar2[i]) + bhr);
            float zg = sigmoid_ap(pxz[i] + hsum2(az2[i]) + bhz);
            float ng = tanh_ap(pxn[i] + rg * (hsum2(an2[i]) + bhn));
            float hold = sH[(rq * 4 + i) * H + jj];
            float hnew = (1.f - zg) * ng + zg * hold;
            hnext[(size_t)row * H + jj] = hnew;
            if (h_seq) h_seq[((size_t)row * S + t) * H + jj] = hnew;
            if (h_final && t == S - 1) h_final[(size_t)row * H + jj] = hnew;
        }

        target++;
        group_barrier(rowtile, target);
    }
}

// -------- projection + 96-step diagonal forecast, fused --------
__global__ void forecast_kernel(
    const float* __restrict__ h2, const float* __restrict__ Wp,
    const float* __restrict__ bp, const float* __restrict__ C,
    const float* __restrict__ rld, const float* __restrict__ rtd,
    const float* __restrict__ rg_, const float* __restrict__ om,
    float* __restrict__ out)
{
    const int b = blockIdx.x;   // 256
    const int d = threadIdx.x;  // 32
    __shared__ float sh[H];
    for (int i = d; i < H; i += 32) sh[i] = h2[(size_t)b * H + i];
    __syncthreads();

    float s[NSTATE];
#pragma unroll
    for (int st = 0; st < NSTATE; st++) {
        const float* w = Wp + (size_t)(d * NSTATE + st) * H;
        float acc = bp[d * NSTATE + st];
        for (int k = 0; k < H; k += 4) {
            float4 wv = *(const float4*)(w + k);
            acc += sh[k] * wv.x + sh[k + 1] * wv.y + sh[k + 2] * wv.z + sh[k + 3] * wv.w;
        }
        s[st] = acc;
    }

    float al = 1.f / (1.f + expf(-rld[d])) * 0.15f + 0.85f;
    float at = 1.f / (1.f + expf(-rtd[d])) * 0.25f + 0.70f;
    float gg = 1.f / (1.f + expf(-rg_[d])) * 0.20f + 0.80f;
    float c = cosf(om[d]), sn = sinf(om[d]);
    float r00 = gg * c, r01 = -gg * sn, r10 = gg * sn, r11 = gg * c;
    float C0 = C[d * 4 + 0], C1 = C[d * 4 + 1], C2 = C[d * 4 + 2], C3 = C[d * 4 + 3];

    for (int p = 0; p < PRED; p++) {
        float n0 = s[0] * al;
        float n1 = s[1] * at;
        float n2 = s[2] * r00 + s[3] * r10;
        float n3 = s[2] * r01 + s[3] * r11;
        s[0] = n0; s[1] = n1; s[2] = n2; s[3] = n3;
        out[((size_t)b * PRED + p) * D_OUT + d] = C0 * n0 + C1 * n1 + C2 * n2 + C3 * n3;
    }
}

extern "C" void kernel_launch(void* const* d_in, const int* in_sizes, int n_in,
                              void* d_out, int out_size)
{
    const float* x    = (const float*)d_in[0];
    const float* Wih0 = (const float*)d_in[1];
    const float* Whh0 = (const float*)d_in[2];
    const float* bih0 = (const float*)d_in[3];
    const float* bhh0 = (const float*)d_in[4];
    const float* Wih1 = (const float*)d_in[5];
    const float* Whh1 = (const float*)d_in[6];
    const float* bih1 = (const float*)d_in[7];
    const float* bhh1 = (const float*)d_in[8];
    const float* Wp   = (const float*)d_in[9];
    const float* bp   = (const float*)d_in[10];
    const float* C    = (const float*)d_in[11];
    const float* rld  = (const float*)d_in[12];
    const float* rtd  = (const float*)d_in[13];
    const float* rg   = (const float*)d_in[14];
    const float* om   = (const float*)d_in[15];
    float* out = (float*)d_out;

    float *xp, *h1s, *h2;
    cudaGetSymbolAddress((void**)&xp, g_xp);
    cudaGetSymbolAddress((void**)&h1s, g_h1s);
    cudaGetSymbolAddress((void**)&h2, g_h2);

    cudaFuncSetAttribute(gru_layer, cudaFuncAttributeMaxDynamicSharedMemorySize, SMEM_BYTES);

    dim3 gg(G3 / 64, (B * S) / 64);

    gemm_nt_bias<<<gg, 256>>>(x, Wih0, bih0, xp, B * S, G3, IN_F);
    gru_layer<<<GRU_CTAS, 128, SMEM_BYTES>>>(xp, Whh0, bhh0, h1s, nullptr);
    gemm_nt_bias<<<gg, 256>>>(h1s, Wih1, bih1, xp, B * S, G3, H);
    gru_layer<<<GRU_CTAS, 128, SMEM_BYTES>>>(xp, Whh1, bhh1, nullptr, h2);
    forecast_kernel<<<B, 32>>>(h2, Wp, bp, C, rld, rtd, rg, om, out);
}